// round 1
// baseline (speedup 1.0000x reference)
#include <cuda_runtime.h>
#include <cstdio>

#define Bq 2
#define Tq 2048
#define Dq 1024
#define Hq 16
#define Sq 16
#define HDq 64

// ---------------- scratch (static device globals; no allocation) ----------------
__device__ float g_qkv[(size_t)Bq * Tq * 3 * Dq];     // (B*T, 3072): [q|k|v] per token
__device__ float g_centers[Hq * Sq * HDq];
__device__ float g_invvar[Hq * Sq];
__device__ float g_amps[Hq * Sq];
__device__ float g_qw[(size_t)Bq * Hq * Tq * Sq];     // q_weights * (1/temp applied later)
__device__ float g_kw[(size_t)Bq * Hq * Tq * Sq];     // k_weights * amplitude
__device__ float g_attn[(size_t)Bq * Tq * Dq];        // attention @ v, (B,T,D)

// ---------------- prep: centers, inv_var, amplitudes ----------------
__global__ void prep_kernel(const float* __restrict__ centers_in,
                            const float* __restrict__ deltas,
                            const float* __restrict__ log_scales,
                            const float* __restrict__ log_amps,
                            const float* __restrict__ movement_scale) {
    int tid = threadIdx.x;
    float ms = *movement_scale;
    float sig = 1.0f / (1.0f + expf(-ms));
    int i = blockIdx.x * 256 + tid;             // grid 64 * 256 = 16384 = H*S*HD
    g_centers[i] = centers_in[i] + deltas[i] * sig * 0.2f;
    if (blockIdx.x == 0) {                      // tid covers H*S = 256
        float sc = expf(log_scales[tid]);
        sc = fminf(fmaxf(sc, 0.01f), 2.0f);
        g_invvar[tid] = -0.5f / (sc * sc + 1e-8f);
        float am = expf(log_amps[tid]);
        g_amps[tid] = fminf(fmaxf(am, 1e-6f), 10.0f);
    }
}

// ---------------- fp32 NT GEMM: C[n,m] = sum_k A[n,k] * B[m,k] ----------------
// 128x128 tile, BK=8, 256 threads, 8x8 per thread.
__global__ __launch_bounds__(256) void sgemm_nt(const float* __restrict__ A,
                                                const float* __restrict__ B,
                                                float* __restrict__ C,
                                                int N, int M, int K) {
    __shared__ float As[8][128];
    __shared__ float Bs[8][128];
    const int tid = threadIdx.x;
    const int bn = blockIdx.y * 128;
    const int bm = blockIdx.x * 128;
    const int tx = tid & 15;
    const int ty = tid >> 4;
    const int lrow = tid >> 1;           // 0..127
    const int lk = (tid & 1) << 2;       // 0 or 4

    float acc[8][8];
#pragma unroll
    for (int i = 0; i < 8; i++)
#pragma unroll
        for (int j = 0; j < 8; j++) acc[i][j] = 0.f;

    const float* Ap = A + (size_t)(bn + lrow) * K + lk;
    const float* Bp = B + (size_t)(bm + lrow) * K + lk;

    for (int k0 = 0; k0 < K; k0 += 8) {
        float4 a = *(const float4*)(Ap + k0);
        float4 b = *(const float4*)(Bp + k0);
        __syncthreads();
        As[lk + 0][lrow] = a.x; As[lk + 1][lrow] = a.y;
        As[lk + 2][lrow] = a.z; As[lk + 3][lrow] = a.w;
        Bs[lk + 0][lrow] = b.x; Bs[lk + 1][lrow] = b.y;
        Bs[lk + 2][lrow] = b.z; Bs[lk + 3][lrow] = b.w;
        __syncthreads();
#pragma unroll
        for (int k = 0; k < 8; k++) {
            float af[8], bf[8];
#pragma unroll
            for (int i = 0; i < 8; i++) af[i] = As[k][ty * 8 + i];
#pragma unroll
            for (int j = 0; j < 8; j++) bf[j] = Bs[k][tx * 8 + j];
#pragma unroll
            for (int i = 0; i < 8; i++)
#pragma unroll
                for (int j = 0; j < 8; j++) acc[i][j] += af[i] * bf[j];
        }
    }
#pragma unroll
    for (int i = 0; i < 8; i++) {
        float* crow = C + (size_t)(bn + ty * 8 + i) * M + bm + tx * 8;
#pragma unroll
        for (int j = 0; j < 8; j += 4) {
            float4 v = make_float4(acc[i][j], acc[i][j + 1], acc[i][j + 2], acc[i][j + 3]);
            *(float4*)(crow + j) = v;
        }
    }
}

// ---------------- splat gaussian weights ----------------
// grid (T/16, H, B*2) z: b = z>>1, which = z&1 (0=q -> g_qw, 1=k -> g_kw*amp)
__global__ __launch_bounds__(256) void splat_weights_kernel() {
    __shared__ float sx[16][68];
    __shared__ float sc[16][68];
    const int tid = threadIdx.x;
    const int tb = blockIdx.x;
    const int h = blockIdx.y;
    const int b = blockIdx.z >> 1;
    const int which = blockIdx.z & 1;

    const int row = tid >> 4;            // 0..15
    const int d4 = (tid & 15) << 2;      // 0..60

    const int t = tb * 16 + row;
    float4 xv = *(const float4*)(g_qkv + ((size_t)(b * Tq + t) * 3 + which) * Dq + h * HDq + d4);
    *(float4*)&sx[row][d4] = xv;
    float4 cv = *(const float4*)(g_centers + (h * Sq + row) * HDq + d4);
    *(float4*)&sc[row][d4] = cv;
    __syncthreads();

    const int s = tid & 15;
    const int ti = tid >> 4;
    float acc = 0.f;
#pragma unroll
    for (int d = 0; d < 64; d++) {
        float diff = sx[ti][d] - sc[s][d];
        acc += diff * diff;
    }
    float w = __expf(acc * g_invvar[h * Sq + s]);
    if (which) w *= g_amps[h * Sq + s];
    float* dst = which ? g_kw : g_qw;
    dst[(((size_t)b * Hq + h) * Tq + (tb * 16 + ti)) * Sq + s] = w;
}

// ---------------- flash attention over splat weights ----------------
// logits[i,j] = sum_s qw[i,s]*kw_amp[j,s]; softmax over j; out = P @ V
// grid (T/64, H, B), 64 threads, one query row per thread.
__global__ __launch_bounds__(64) void flash_kernel(const float* __restrict__ temperature) {
    __shared__ float skw[64][16];
    __shared__ float sv[64][64];
    const int tid = threadIdx.x;
    const int ib = blockIdx.x, h = blockIdx.y, b = blockIdx.z;

    float temp = fminf(fmaxf(*temperature, 0.1f), 10.0f);
    float invtemp = 1.0f / temp;

    const int t = ib * 64 + tid;
    float qw[16];
    const float* qp = g_qw + (((size_t)b * Hq + h) * Tq + t) * Sq;
#pragma unroll
    for (int s = 0; s < 16; s++) qw[s] = qp[s] * invtemp;

    float acc[64];
#pragma unroll
    for (int d = 0; d < 64; d++) acc[d] = 0.f;
    float m = -1e30f, l = 0.f;

    for (int jt = 0; jt < Tq; jt += 64) {
        __syncthreads();
        // load KW tile (64 x 16)
        const float* kbase = g_kw + (((size_t)b * Hq + h) * Tq + jt) * Sq;
#pragma unroll
        for (int r = 0; r < 4; r++) {
            int idx = r * 64 + tid;
            int rr = idx >> 2, c4 = (idx & 3) << 2;
            *(float4*)&skw[rr][c4] = *(const float4*)(kbase + rr * 16 + c4);
        }
        // load V tile (64 x 64)
#pragma unroll
        for (int r = 0; r < 16; r++) {
            int idx = r * 64 + tid;
            int rr = idx >> 4, c4 = (idx & 15) << 2;
            *(float4*)&sv[rr][c4] =
                *(const float4*)(g_qkv + ((size_t)((b * Tq + jt + rr) * 3 + 2)) * Dq + h * HDq + c4);
        }
        __syncthreads();

#pragma unroll
        for (int jc = 0; jc < 64; jc += 16) {
            float lt[16];
            float cmax = -1e30f;
#pragma unroll
            for (int jj = 0; jj < 16; jj++) {
                float d0 = 0.f;
#pragma unroll
                for (int s = 0; s < 16; s++) d0 += qw[s] * skw[jc + jj][s];
                lt[jj] = d0;
                cmax = fmaxf(cmax, d0);
            }
            float newm = fmaxf(m, cmax);
            float scale = __expf(m - newm);
            m = newm;
            l *= scale;
#pragma unroll
            for (int d = 0; d < 64; d++) acc[d] *= scale;
#pragma unroll
            for (int jj = 0; jj < 16; jj++) {
                float p = __expf(lt[jj] - m);
                l += p;
#pragma unroll
                for (int d = 0; d < 64; d++) acc[d] += p * sv[jc + jj][d];
            }
        }
    }

    float invl = 1.0f / l;
    float* dst = g_attn + ((size_t)(b * Tq + t)) * Dq + h * HDq;
#pragma unroll
    for (int d = 0; d < 64; d += 4) {
        float4 v = make_float4(acc[d] * invl, acc[d + 1] * invl, acc[d + 2] * invl, acc[d + 3] * invl);
        *(float4*)(dst + d) = v;
    }
}

// ---------------- launch ----------------
extern "C" void kernel_launch(void* const* d_in, const int* in_sizes, int n_in,
                              void* d_out, int out_size) {
    const float* x            = (const float*)d_in[0];
    const float* centers      = (const float*)d_in[1];
    const float* deltas       = (const float*)d_in[2];
    const float* log_scales   = (const float*)d_in[3];
    const float* log_amps     = (const float*)d_in[4];
    const float* movement     = (const float*)d_in[5];
    const float* temperature  = (const float*)d_in[6];
    const float* qkv_w        = (const float*)d_in[7];
    const float* out_w        = (const float*)d_in[8];
    float* out = (float*)d_out;

    void *p_qkv = nullptr, *p_attn = nullptr;
    cudaGetSymbolAddress(&p_qkv, g_qkv);
    cudaGetSymbolAddress(&p_attn, g_attn);
    float* qkv_buf  = (float*)p_qkv;
    float* attn_buf = (float*)p_attn;

    prep_kernel<<<64, 256>>>(centers, deltas, log_scales, log_amps, movement);

    // qkv = x @ qkv_w.T : (4096,1024) x (3072,1024)^T
    sgemm_nt<<<dim3(3072 / 128, 4096 / 128), 256>>>(x, qkv_w, qkv_buf, Bq * Tq, 3 * Dq, Dq);

    // gaussian splat weights for q and k
    splat_weights_kernel<<<dim3(Tq / 16, Hq, Bq * 2), 256>>>();

    // streamed softmax attention
    flash_kernel<<<dim3(Tq / 64, Hq, Bq), 64>>>(temperature);

    // out = attn_out @ out_w.T : (4096,1024) x (1024,1024)^T
    sgemm_nt<<<dim3(1024 / 128, 4096 / 128), 256>>>(attn_buf, out_w, out, Bq * Tq, Dq, Dq);
}

// round 3
// speedup vs baseline: 1.9304x; 1.9304x over previous
#include <cuda_runtime.h>
#include <cuda_bf16.h>
#include <cstdint>

#define Bq 2
#define Tq 2048
#define Dq 1024
#define Hq 16
#define Sq 16
#define HDq 64

// ---------------- scratch (static device globals; no allocation) ----------------
__device__ __align__(128) float g_qkv[(size_t)Bq * Tq * 3 * Dq];   // (B*T, 3072)
__device__ __align__(128) float g_centers[Hq * Sq * HDq];
__device__ __align__(128) float g_invvar[Hq * Sq];
__device__ __align__(128) float g_amps[Hq * Sq];
__device__ __align__(128) float g_qw[(size_t)Bq * Hq * Tq * Sq];
__device__ __align__(128) float g_kw[(size_t)Bq * Hq * Tq * Sq];
__device__ __align__(128) float g_attn[(size_t)Bq * Tq * Dq];
// split-K partials: [B][H][T][4][68] (64 acc + 1 l + pad)
__device__ __align__(128) float g_part[(size_t)Bq * Hq * Tq * 4 * 68];

// ---------------- prep ----------------
__global__ void prep_kernel(const float* __restrict__ centers_in,
                            const float* __restrict__ deltas,
                            const float* __restrict__ log_scales,
                            const float* __restrict__ log_amps,
                            const float* __restrict__ movement_scale) {
    int tid = threadIdx.x;
    float ms = *movement_scale;
    float sig = 1.0f / (1.0f + expf(-ms));
    int i = blockIdx.x * 256 + tid;
    g_centers[i] = centers_in[i] + deltas[i] * sig * 0.2f;
    if (blockIdx.x == 0) {
        float sc = expf(log_scales[tid]);
        sc = fminf(fmaxf(sc, 0.01f), 2.0f);
        g_invvar[tid] = -0.5f / (sc * sc + 1e-8f);
        float am = expf(log_amps[tid]);
        g_amps[tid] = fminf(fmaxf(am, 1e-6f), 10.0f);
    }
}

// ---------------- bf16x3 tensor-core NT GEMM: C[n,m] = sum_k A[n,k] B[m,k] ----------------
// mma.sync.m16n8k16 bf16 with (hi,lo) split; error ~2^-16 per product.
// Block 128x128x(BK=32), 256 threads = 8 warps as 2x4; warp tile 64x32.
// smem stored in FRAGMENT ORDER so consumers use 1 LDS.128 per A-frag / LDS.64 per B-frag.

__device__ __forceinline__ void mma_bf16(float* c, const uint32_t* a, const uint32_t* b) {
    asm volatile(
        "mma.sync.aligned.m16n8k16.row.col.f32.bf16.bf16.f32 "
        "{%0,%1,%2,%3}, {%4,%5,%6,%7}, {%8,%9}, {%0,%1,%2,%3};"
        : "+f"(c[0]), "+f"(c[1]), "+f"(c[2]), "+f"(c[3])
        : "r"(a[0]), "r"(a[1]), "r"(a[2]), "r"(a[3]), "r"(b[0]), "r"(b[1]));
}

__device__ __forceinline__ void split_pack(float x, float y, uint32_t& hi, uint32_t& lo) {
    __nv_bfloat16 hx = __float2bfloat16(x);
    __nv_bfloat16 hy = __float2bfloat16(y);
    __nv_bfloat16 lx = __float2bfloat16(x - __bfloat162float(hx));
    __nv_bfloat16 ly = __float2bfloat16(y - __bfloat162float(hy));
    __nv_bfloat162 hp = __halves2bfloat162(hx, hy);   // low half = first (even k)
    __nv_bfloat162 lp = __halves2bfloat162(lx, ly);
    hi = *reinterpret_cast<uint32_t*>(&hp);
    lo = *reinterpret_cast<uint32_t*>(&lp);
}

__global__ __launch_bounds__(256) void mma_gemm_nt(const float* __restrict__ A,
                                                   const float* __restrict__ B,
                                                   float* __restrict__ C,
                                                   int N, int M, int K) {
    // A frags: [v][mt(8)][ks(2)][lane(32)][reg(4)]  -> 2*8*2*32*4 = 4096 u32 (16KB)
    // B frags: [v][nt(16)][ks(2)][lane(32)][reg(2)] -> 2*16*2*32*2 = 4096 u32 (16KB)
    __shared__ uint32_t sA[4096];
    __shared__ uint32_t sB[4096];

    const int tid = threadIdx.x;
    const int warp = tid >> 5;
    const int lid = tid & 31;
    const int wm = warp >> 2;         // 0..1
    const int wn = warp & 3;          // 0..3
    const int bn = blockIdx.y * 128;
    const int bm = blockIdx.x * 128;

    const int lr = tid >> 3;          // base row 0..31
    const int kc4 = (tid & 7) << 2;   // k offset within BK: 0,4,...,28

    float acc[4][4][4];
#pragma unroll
    for (int i = 0; i < 4; i++)
#pragma unroll
        for (int j = 0; j < 4; j++)
#pragma unroll
            for (int r = 0; r < 4; r++) acc[i][j][r] = 0.f;

    const int KCH = K >> 5;
    for (int kc = 0; kc < KCH; kc++) {
        __syncthreads();
        // ---- load + split + fragment-order store ----
#pragma unroll
        for (int i = 0; i < 4; i++) {
            int row = lr + 32 * i;
            // A
            float4 a = *(const float4*)(A + (size_t)(bn + row) * K + kc * 32 + kc4);
            int mt = row >> 4, rr = row & 15;
            {
                int kp = kc4, kk = kp & 15, ks = kp >> 4;
                int lane = ((rr & 7) << 2) | ((kk & 7) >> 1);
                int reg = (rr >> 3) + ((kk >> 3) << 1);
                int base = ((mt * 2 + ks) * 32 + lane) * 4 + reg;
                uint32_t hi, lo;
                split_pack(a.x, a.y, hi, lo);
                sA[base] = hi; sA[2048 + base] = lo;
            }
            {
                int kp = kc4 + 2, kk = kp & 15, ks = kp >> 4;
                int lane = ((rr & 7) << 2) | ((kk & 7) >> 1);
                int reg = (rr >> 3) + ((kk >> 3) << 1);
                int base = ((mt * 2 + ks) * 32 + lane) * 4 + reg;
                uint32_t hi, lo;
                split_pack(a.z, a.w, hi, lo);
                sA[base] = hi; sA[2048 + base] = lo;
            }
            // B
            float4 b = *(const float4*)(B + (size_t)(bm + row) * K + kc * 32 + kc4);
            int nt = row >> 3, nn = row & 7;
            {
                int kp = kc4, kk = kp & 15, ks = kp >> 4;
                int lane = (nn << 2) | ((kk & 7) >> 1);
                int reg = kk >> 3;
                int base = ((nt * 2 + ks) * 32 + lane) * 2 + reg;
                uint32_t hi, lo;
                split_pack(b.x, b.y, hi, lo);
                sB[base] = hi; sB[2048 + base] = lo;
            }
            {
                int kp = kc4 + 2, kk = kp & 15, ks = kp >> 4;
                int lane = (nn << 2) | ((kk & 7) >> 1);
                int reg = kk >> 3;
                int base = ((nt * 2 + ks) * 32 + lane) * 2 + reg;
                uint32_t hi, lo;
                split_pack(b.z, b.w, hi, lo);
                sB[base] = hi; sB[2048 + base] = lo;
            }
        }
        __syncthreads();

        // ---- consume: 2 k-steps, 4x4 mma tiles, 3 products each ----
#pragma unroll
        for (int ks = 0; ks < 2; ks++) {
            uint32_t ahi[4][4], alo[4][4], bhi[4][2], blo[4][2];
#pragma unroll
            for (int i = 0; i < 4; i++) {
                int mt = wm * 4 + i;
                uint4 h = *(const uint4*)&sA[((mt * 2 + ks) * 32 + lid) * 4];
                ahi[i][0] = h.x; ahi[i][1] = h.y; ahi[i][2] = h.z; ahi[i][3] = h.w;
                uint4 l = *(const uint4*)&sA[2048 + ((mt * 2 + ks) * 32 + lid) * 4];
                alo[i][0] = l.x; alo[i][1] = l.y; alo[i][2] = l.z; alo[i][3] = l.w;
            }
#pragma unroll
            for (int j = 0; j < 4; j++) {
                int nt = wn * 4 + j;
                uint2 h = *(const uint2*)&sB[((nt * 2 + ks) * 32 + lid) * 2];
                bhi[j][0] = h.x; bhi[j][1] = h.y;
                uint2 l = *(const uint2*)&sB[2048 + ((nt * 2 + ks) * 32 + lid) * 2];
                blo[j][0] = l.x; blo[j][1] = l.y;
            }
#pragma unroll
            for (int i = 0; i < 4; i++)
#pragma unroll
                for (int j = 0; j < 4; j++) {
                    mma_bf16(acc[i][j], ahi[i], bhi[j]);
                    mma_bf16(acc[i][j], ahi[i], blo[j]);
                    mma_bf16(acc[i][j], alo[i], bhi[j]);
                }
        }
    }

    // ---- epilogue ----
#pragma unroll
    for (int i = 0; i < 4; i++) {
        int row0 = bn + wm * 64 + i * 16 + (lid >> 2);
#pragma unroll
        for (int j = 0; j < 4; j++) {
            int col = bm + wn * 32 + j * 8 + (lid & 3) * 2;
            *(float2*)(C + (size_t)row0 * M + col) = make_float2(acc[i][j][0], acc[i][j][1]);
            *(float2*)(C + (size_t)(row0 + 8) * M + col) = make_float2(acc[i][j][2], acc[i][j][3]);
        }
    }
}

// ---------------- splat gaussian weights ----------------
__global__ __launch_bounds__(256) void splat_weights_kernel() {
    __shared__ float sx[16][68];
    __shared__ float sc[16][68];
    const int tid = threadIdx.x;
    const int tb = blockIdx.x;
    const int h = blockIdx.y;
    const int b = blockIdx.z >> 1;
    const int which = blockIdx.z & 1;

    const int row = tid >> 4;
    const int d4 = (tid & 15) << 2;

    const int t = tb * 16 + row;
    float4 xv = *(const float4*)(g_qkv + ((size_t)(b * Tq + t) * 3 + which) * Dq + h * HDq + d4);
    *(float4*)&sx[row][d4] = xv;
    float4 cv = *(const float4*)(g_centers + (h * Sq + row) * HDq + d4);
    *(float4*)&sc[row][d4] = cv;
    __syncthreads();

    const int s = tid & 15;
    const int ti = tid >> 4;
    float acc = 0.f;
#pragma unroll
    for (int d = 0; d < 64; d++) {
        float diff = sx[ti][d] - sc[s][d];
        acc += diff * diff;
    }
    float w = __expf(acc * g_invvar[h * Sq + s]);
    if (which) w *= g_amps[h * Sq + s];
    float* dst = which ? g_kw : g_qw;
    dst[(((size_t)b * Hq + h) * Tq + (tb * 16 + ti)) * Sq + s] = w;
}

// ---------------- flash partial (split-K over keys, fixed-bound softmax) ----------------
// grid (T/64, H, B*4); z = b*4 + kc. Each block: 64 queries x 512 keys -> partial acc,l.
__global__ __launch_bounds__(64) void flash_partial(const float* __restrict__ temperature) {
    __shared__ float skw[64][16];
    __shared__ float sv[64][64];
    const int tid = threadIdx.x;
    const int ib = blockIdx.x, h = blockIdx.y;
    const int b = blockIdx.z >> 2, kchunk = blockIdx.z & 3;

    float temp = fminf(fmaxf(*temperature, 0.1f), 10.0f);
    float invtemp = 1.0f / temp;
    float asum = 0.f;
#pragma unroll
    for (int s = 0; s < 16; s++) asum += g_amps[h * 16 + s];
    const float bound = asum * invtemp;   // logits/temp <= bound (qw,kw in (0,1])

    const int t = ib * 64 + tid;
    float qw[16];
    const float* qp = g_qw + (((size_t)b * Hq + h) * Tq + t) * Sq;
#pragma unroll
    for (int s = 0; s < 16; s++) qw[s] = qp[s] * invtemp;

    float acc[64];
#pragma unroll
    for (int d = 0; d < 64; d++) acc[d] = 0.f;
    float l = 0.f;

    const int key0 = kchunk * 512;
    for (int jt = 0; jt < 512; jt += 64) {
        __syncthreads();
        const float* kbase = g_kw + (((size_t)b * Hq + h) * Tq + key0 + jt) * Sq;
#pragma unroll
        for (int r = 0; r < 4; r++) {
            int idx = r * 64 + tid;
            int rr = idx >> 2, c4 = (idx & 3) << 2;
            *(float4*)&skw[rr][c4] = *(const float4*)(kbase + rr * 16 + c4);
        }
#pragma unroll
        for (int r = 0; r < 16; r++) {
            int idx = r * 64 + tid;
            int rr = idx >> 4, c4 = (idx & 15) << 2;
            *(float4*)&sv[rr][c4] =
                *(const float4*)(g_qkv + ((size_t)((b * Tq + key0 + jt + rr) * 3 + 2)) * Dq + h * HDq + c4);
        }
        __syncthreads();

#pragma unroll 4
        for (int jj = 0; jj < 64; jj++) {
            float d0 = 0.f;
#pragma unroll
            for (int s = 0; s < 16; s++) d0 += qw[s] * skw[jj][s];
            float p = __expf(d0 - bound);
            l += p;
            const float4* vr = (const float4*)sv[jj];
#pragma unroll
            for (int d = 0; d < 16; d++) {
                float4 v = vr[d];
                acc[d * 4 + 0] += p * v.x;
                acc[d * 4 + 1] += p * v.y;
                acc[d * 4 + 2] += p * v.z;
                acc[d * 4 + 3] += p * v.w;
            }
        }
    }

    float* po = g_part + ((((((size_t)b * Hq + h) * Tq + t) * 4) + kchunk)) * 68;
#pragma unroll
    for (int d = 0; d < 64; d += 4)
        *(float4*)(po + d) = make_float4(acc[d], acc[d + 1], acc[d + 2], acc[d + 3]);
    po[64] = l;
}

// ---------------- combine partials ----------------
__global__ __launch_bounds__(128) void flash_combine() {
    int rid = blockIdx.x * 4 + (threadIdx.x >> 5);
    int lane = threadIdx.x & 31;
    int b = rid >> 15;            // H*T = 32768
    int ht = rid & 32767;
    int h = ht >> 11;
    int t = ht & 2047;
    const float* p = g_part + (size_t)rid * 4 * 68;
    float a0 = 0.f, a1 = 0.f, l = 0.f;
#pragma unroll
    for (int c = 0; c < 4; c++) {
        a0 += p[c * 68 + lane];
        a1 += p[c * 68 + 32 + lane];
        l += p[c * 68 + 64];
    }
    float inv = 1.0f / l;
    float* dst = g_attn + ((size_t)(b * Tq + t)) * Dq + h * 64;
    dst[lane] = a0 * inv;
    dst[lane + 32] = a1 * inv;
}

// ---------------- launch ----------------
extern "C" void kernel_launch(void* const* d_in, const int* in_sizes, int n_in,
                              void* d_out, int out_size) {
    const float* x           = (const float*)d_in[0];
    const float* centers     = (const float*)d_in[1];
    const float* deltas      = (const float*)d_in[2];
    const float* log_scales  = (const float*)d_in[3];
    const float* log_amps    = (const float*)d_in[4];
    const float* movement    = (const float*)d_in[5];
    const float* temperature = (const float*)d_in[6];
    const float* qkv_w       = (const float*)d_in[7];
    const float* out_w       = (const float*)d_in[8];
    float* out = (float*)d_out;

    void *p_qkv = nullptr, *p_attn = nullptr;
    cudaGetSymbolAddress(&p_qkv, g_qkv);
    cudaGetSymbolAddress(&p_attn, g_attn);
    float* qkv_buf = (float*)p_qkv;
    float* attn_buf = (float*)p_attn;

    prep_kernel<<<64, 256>>>(centers, deltas, log_scales, log_amps, movement);

    // qkv = x @ qkv_w.T : N=4096, M=3072, K=1024
    mma_gemm_nt<<<dim3(3072 / 128, 4096 / 128), 256>>>(x, qkv_w, qkv_buf, Bq * Tq, 3 * Dq, Dq);

    splat_weights_kernel<<<dim3(Tq / 16, Hq, Bq * 2), 256>>>();

    flash_partial<<<dim3(Tq / 64, Hq, Bq * 4), 64>>>(temperature);
    flash_combine<<<Bq * Hq * Tq / 4, 128>>>();

    // out = attn @ out_w.T : N=4096, M=1024, K=1024
    mma_gemm_nt<<<dim3(1024 / 128, 4096 / 128), 256>>>(attn_buf, out_w, out, Bq * Tq, Dq, Dq);
}

// round 4
// speedup vs baseline: 2.6102x; 1.3522x over previous
#include <cuda_runtime.h>
#include <cuda_bf16.h>
#include <cstdint>

#define Bq 2
#define Tq 2048
#define Dq 1024
#define Hq 16
#define Sq 16
#define HDq 64

// ---------------- scratch (static device globals; no allocation) ----------------
__device__ __align__(128) float g_qkv[(size_t)Bq * Tq * 3 * Dq];   // (B*T, 3072)
__device__ __align__(128) float g_centers[Hq * Sq * HDq];
__device__ __align__(128) float g_invvar[Hq * Sq];
__device__ __align__(128) float g_amps[Hq * Sq];
__device__ __align__(128) float g_qw[(size_t)Bq * Hq * Tq * Sq];
__device__ __align__(128) float g_kw[(size_t)Bq * Hq * Tq * Sq];
__device__ __align__(128) float g_attn[(size_t)Bq * Tq * Dq];

// ---------------- helpers ----------------
__device__ __forceinline__ void mma_bf16(float* c, const uint32_t* a, const uint32_t* b) {
    asm volatile(
        "mma.sync.aligned.m16n8k16.row.col.f32.bf16.bf16.f32 "
        "{%0,%1,%2,%3}, {%4,%5,%6,%7}, {%8,%9}, {%0,%1,%2,%3};"
        : "+f"(c[0]), "+f"(c[1]), "+f"(c[2]), "+f"(c[3])
        : "r"(a[0]), "r"(a[1]), "r"(a[2]), "r"(a[3]), "r"(b[0]), "r"(b[1]));
}

// pack {lo half = x (even k), hi half = y (odd k)}
__device__ __forceinline__ uint32_t pack_bf16x2(float x, float y) {
    uint32_t r;
    asm("cvt.rn.bf16x2.f32 %0, %1, %2;" : "=r"(r) : "f"(y), "f"(x));
    return r;
}
// hi = bf16 pair of (x,y); lo = bf16 pair of residuals
__device__ __forceinline__ void split2(float x, float y, uint32_t& hi, uint32_t& lo) {
    hi = pack_bf16x2(x, y);
    float hx = __uint_as_float(hi << 16);
    float hy = __uint_as_float(hi & 0xffff0000u);
    lo = pack_bf16x2(x - hx, y - hy);
}

__device__ __forceinline__ void split_pack(float x, float y, uint32_t& hi, uint32_t& lo) {
    split2(x, y, hi, lo);
}

// ---------------- prep ----------------
__global__ void prep_kernel(const float* __restrict__ centers_in,
                            const float* __restrict__ deltas,
                            const float* __restrict__ log_scales,
                            const float* __restrict__ log_amps,
                            const float* __restrict__ movement_scale) {
    int tid = threadIdx.x;
    float ms = *movement_scale;
    float sig = 1.0f / (1.0f + expf(-ms));
    int i = blockIdx.x * 256 + tid;
    g_centers[i] = centers_in[i] + deltas[i] * sig * 0.2f;
    if (blockIdx.x == 0) {
        float sc = expf(log_scales[tid]);
        sc = fminf(fmaxf(sc, 0.01f), 2.0f);
        g_invvar[tid] = -0.5f / (sc * sc + 1e-8f);
        float am = expf(log_amps[tid]);
        g_amps[tid] = fminf(fmaxf(am, 1e-6f), 10.0f);
    }
}

// ---------------- bf16x3 tensor-core NT GEMM (unchanged from R3) ----------------
__global__ __launch_bounds__(256) void mma_gemm_nt(const float* __restrict__ A,
                                                   const float* __restrict__ B,
                                                   float* __restrict__ C,
                                                   int N, int M, int K) {
    __shared__ uint32_t sA[4096];
    __shared__ uint32_t sB[4096];

    const int tid = threadIdx.x;
    const int warp = tid >> 5;
    const int lid = tid & 31;
    const int wm = warp >> 2;
    const int wn = warp & 3;
    const int bn = blockIdx.y * 128;
    const int bm = blockIdx.x * 128;

    const int lr = tid >> 3;
    const int kc4 = (tid & 7) << 2;

    float acc[4][4][4];
#pragma unroll
    for (int i = 0; i < 4; i++)
#pragma unroll
        for (int j = 0; j < 4; j++)
#pragma unroll
            for (int r = 0; r < 4; r++) acc[i][j][r] = 0.f;

    const int KCH = K >> 5;
    for (int kc = 0; kc < KCH; kc++) {
        __syncthreads();
#pragma unroll
        for (int i = 0; i < 4; i++) {
            int row = lr + 32 * i;
            float4 a = *(const float4*)(A + (size_t)(bn + row) * K + kc * 32 + kc4);
            int mt = row >> 4, rr = row & 15;
            {
                int kp = kc4, kk = kp & 15, ks = kp >> 4;
                int lane = ((rr & 7) << 2) | ((kk & 7) >> 1);
                int reg = (rr >> 3) + ((kk >> 3) << 1);
                int base = ((mt * 2 + ks) * 32 + lane) * 4 + reg;
                uint32_t hi, lo;
                split_pack(a.x, a.y, hi, lo);
                sA[base] = hi; sA[2048 + base] = lo;
            }
            {
                int kp = kc4 + 2, kk = kp & 15, ks = kp >> 4;
                int lane = ((rr & 7) << 2) | ((kk & 7) >> 1);
                int reg = (rr >> 3) + ((kk >> 3) << 1);
                int base = ((mt * 2 + ks) * 32 + lane) * 4 + reg;
                uint32_t hi, lo;
                split_pack(a.z, a.w, hi, lo);
                sA[base] = hi; sA[2048 + base] = lo;
            }
            float4 b = *(const float4*)(B + (size_t)(bm + row) * K + kc * 32 + kc4);
            int nt = row >> 3, nn = row & 7;
            {
                int kp = kc4, kk = kp & 15, ks = kp >> 4;
                int lane = (nn << 2) | ((kk & 7) >> 1);
                int reg = kk >> 3;
                int base = ((nt * 2 + ks) * 32 + lane) * 2 + reg;
                uint32_t hi, lo;
                split_pack(b.x, b.y, hi, lo);
                sB[base] = hi; sB[2048 + base] = lo;
            }
            {
                int kp = kc4 + 2, kk = kp & 15, ks = kp >> 4;
                int lane = (nn << 2) | ((kk & 7) >> 1);
                int reg = kk >> 3;
                int base = ((nt * 2 + ks) * 32 + lane) * 2 + reg;
                uint32_t hi, lo;
                split_pack(b.z, b.w, hi, lo);
                sB[base] = hi; sB[2048 + base] = lo;
            }
        }
        __syncthreads();

#pragma unroll
        for (int ks = 0; ks < 2; ks++) {
            uint32_t ahi[4][4], alo[4][4], bhi[4][2], blo[4][2];
#pragma unroll
            for (int i = 0; i < 4; i++) {
                int mt = wm * 4 + i;
                uint4 h = *(const uint4*)&sA[((mt * 2 + ks) * 32 + lid) * 4];
                ahi[i][0] = h.x; ahi[i][1] = h.y; ahi[i][2] = h.z; ahi[i][3] = h.w;
                uint4 l = *(const uint4*)&sA[2048 + ((mt * 2 + ks) * 32 + lid) * 4];
                alo[i][0] = l.x; alo[i][1] = l.y; alo[i][2] = l.z; alo[i][3] = l.w;
            }
#pragma unroll
            for (int j = 0; j < 4; j++) {
                int nt = wn * 4 + j;
                uint2 h = *(const uint2*)&sB[((nt * 2 + ks) * 32 + lid) * 2];
                bhi[j][0] = h.x; bhi[j][1] = h.y;
                uint2 l = *(const uint2*)&sB[2048 + ((nt * 2 + ks) * 32 + lid) * 2];
                blo[j][0] = l.x; blo[j][1] = l.y;
            }
#pragma unroll
            for (int i = 0; i < 4; i++)
#pragma unroll
                for (int j = 0; j < 4; j++) {
                    mma_bf16(acc[i][j], ahi[i], bhi[j]);
                    mma_bf16(acc[i][j], ahi[i], blo[j]);
                    mma_bf16(acc[i][j], alo[i], bhi[j]);
                }
        }
    }

#pragma unroll
    for (int i = 0; i < 4; i++) {
        int row0 = bn + wm * 64 + i * 16 + (lid >> 2);
#pragma unroll
        for (int j = 0; j < 4; j++) {
            int col = bm + wn * 32 + j * 8 + (lid & 3) * 2;
            *(float2*)(C + (size_t)row0 * M + col) = make_float2(acc[i][j][0], acc[i][j][1]);
            *(float2*)(C + (size_t)(row0 + 8) * M + col) = make_float2(acc[i][j][2], acc[i][j][3]);
        }
    }
}

// ---------------- splat gaussian weights ----------------
__global__ __launch_bounds__(256) void splat_weights_kernel() {
    __shared__ float sx[16][68];
    __shared__ float sc[16][68];
    const int tid = threadIdx.x;
    const int tb = blockIdx.x;
    const int h = blockIdx.y;
    const int b = blockIdx.z >> 1;
    const int which = blockIdx.z & 1;

    const int row = tid >> 4;
    const int d4 = (tid & 15) << 2;

    const int t = tb * 16 + row;
    float4 xv = *(const float4*)(g_qkv + ((size_t)(b * Tq + t) * 3 + which) * Dq + h * HDq + d4);
    *(float4*)&sx[row][d4] = xv;
    float4 cv = *(const float4*)(g_centers + (h * Sq + row) * HDq + d4);
    *(float4*)&sc[row][d4] = cv;
    __syncthreads();

    const int s = tid & 15;
    const int ti = tid >> 4;
    float acc = 0.f;
#pragma unroll
    for (int d = 0; d < 64; d++) {
        float diff = sx[ti][d] - sc[s][d];
        acc += diff * diff;
    }
    float w = __expf(acc * g_invvar[h * Sq + s]);
    if (which) w *= g_amps[h * Sq + s];
    float* dst = which ? g_kw : g_qw;
    dst[(((size_t)b * Hq + h) * Tq + (tb * 16 + ti)) * Sq + s] = w;
}

// ---------------- flash attention, fully tensor-core (bf16x3) ----------------
// grid (T/64, H, B), 128 threads (4 warps). Warp w owns queries [qt*64+w*16, +16).
// logits = QW @ KW^T (k=16), p = exp(logit - bound) register-resident,
// out = P @ V (k=64 per tile) with V staged in B-fragment order.
__global__ __launch_bounds__(128) void flash_mma(const float* __restrict__ temperature) {
    __shared__ float s_kw[64 * 16];
    __shared__ uint32_t s_vhi[2048];   // [nt(8)][ks(4)][lane(32)][reg(2)]
    __shared__ uint32_t s_vlo[2048];

    const int tid = threadIdx.x;
    const int warp = tid >> 5;
    const int lane = tid & 31;
    const int qt = blockIdx.x, h = blockIdx.y, b = blockIdx.z;

    const float temp = fminf(fmaxf(*temperature, 0.1f), 10.0f);
    const float invtemp = 1.0f / temp;
    float asum = 0.f;
#pragma unroll
    for (int s = 0; s < 16; s++) asum += g_amps[h * 16 + s];
    const float bound = asum * invtemp;

    const int r = lane >> 2;            // row within m16 tile
    const int scp = (lane & 3) << 1;    // col pair base
    const int q0 = qt * 64 + warp * 16 + r;

    // Q fragments (constant across key tiles)
    uint32_t qhi[4], qlo[4];
    {
        const float* qwp = g_qw + (((size_t)b * Hq + h) * Tq + q0) * Sq;
        float2 v;
        v = *(const float2*)(qwp + scp);
        split2(v.x * invtemp, v.y * invtemp, qhi[0], qlo[0]);
        v = *(const float2*)(qwp + 8 * Sq + scp);
        split2(v.x * invtemp, v.y * invtemp, qhi[1], qlo[1]);
        v = *(const float2*)(qwp + scp + 8);
        split2(v.x * invtemp, v.y * invtemp, qhi[2], qlo[2]);
        v = *(const float2*)(qwp + 8 * Sq + scp + 8);
        split2(v.x * invtemp, v.y * invtemp, qhi[3], qlo[3]);
    }

    float acc[8][4];
#pragma unroll
    for (int nt = 0; nt < 8; nt++)
#pragma unroll
        for (int i = 0; i < 4; i++) acc[nt][i] = 0.f;
    float lsum0 = 0.f, lsum1 = 0.f;

    const float* kwbase = g_kw + (((size_t)b * Hq + h) * Tq) * Sq;

    for (int kt = 0; kt < 32; kt++) {
        const int key0 = kt * 64;
        __syncthreads();
        // stage kw tile (64x16 fp32)
        {
            const int krow = tid >> 1, koff = (tid & 1) * 8;
            const float* src = kwbase + (key0 + krow) * 16 + koff;
            *(float4*)&s_kw[krow * 16 + koff] = *(const float4*)src;
            *(float4*)&s_kw[krow * 16 + koff + 4] = *(const float4*)(src + 4);
        }
        // stage V tile in B-fragment order (pairs of adjacent keys packed in bf16x2)
#pragma unroll
        for (int i = 0; i < 4; i++) {
            int task = i * 128 + tid;
            int j = task >> 4;          // key pair 0..31
            int c = task & 15;          // d chunk 0..15
            const float* va = g_qkv + ((size_t)(b * Tq + key0 + 2 * j) * 3 + 2) * Dq + h * 64 + c * 4;
            float4 A = *(const float4*)va;
            float4 Bv = *(const float4*)(va + 3 * Dq);
            int ks = j >> 3, rg = (j >> 2) & 1, l4 = j & 3;
            const float* Af = &A.x;
            const float* Bf = &Bv.x;
#pragma unroll
            for (int dd = 0; dd < 4; dd++) {
                int d = c * 4 + dd;
                int nt = d >> 3, nn = d & 7;
                uint32_t hi, lo;
                split2(Af[dd], Bf[dd], hi, lo);
                int idx = ((nt * 4 + ks) * 32 + nn * 4 + l4) * 2 + rg;
                s_vhi[idx] = hi;
                s_vlo[idx] = lo;
            }
        }
        __syncthreads();

        // QK logits + exp + pack P into A-fragments
        uint32_t ahi[4][4], alo[4][4];
#pragma unroll
        for (int nt = 0; nt < 8; nt++) {
            const float* kr = &s_kw[(nt * 8 + r) * 16 + scp];
            float2 k0 = *(const float2*)kr;
            float2 k1 = *(const float2*)(kr + 8);
            uint32_t bh[2], bl[2];
            split2(k0.x, k0.y, bh[0], bl[0]);
            split2(k1.x, k1.y, bh[1], bl[1]);
            float c4[4] = {0.f, 0.f, 0.f, 0.f};
            mma_bf16(c4, qhi, bh);
            mma_bf16(c4, qhi, bl);
            mma_bf16(c4, qlo, bh);
            float p0 = __expf(c4[0] - bound);
            float p1 = __expf(c4[1] - bound);
            float p2 = __expf(c4[2] - bound);
            float p3 = __expf(c4[3] - bound);
            lsum0 += p0 + p1;
            lsum1 += p2 + p3;
            int ks = nt >> 1, ro = (nt & 1) * 2;
            split2(p0, p1, ahi[ks][ro], alo[ks][ro]);
            split2(p2, p3, ahi[ks][ro + 1], alo[ks][ro + 1]);
        }
        // AV
#pragma unroll
        for (int ks = 0; ks < 4; ks++) {
#pragma unroll
            for (int nt = 0; nt < 8; nt++) {
                uint2 vh = *(const uint2*)&s_vhi[((nt * 4 + ks) * 32 + lane) * 2];
                uint2 vl = *(const uint2*)&s_vlo[((nt * 4 + ks) * 32 + lane) * 2];
                uint32_t bh2[2] = {vh.x, vh.y};
                uint32_t bl2[2] = {vl.x, vl.y};
                mma_bf16(acc[nt], ahi[ks], bh2);
                mma_bf16(acc[nt], ahi[ks], bl2);
                mma_bf16(acc[nt], alo[ks], bh2);
            }
        }
    }

    lsum0 += __shfl_xor_sync(0xffffffffu, lsum0, 1);
    lsum0 += __shfl_xor_sync(0xffffffffu, lsum0, 2);
    lsum1 += __shfl_xor_sync(0xffffffffu, lsum1, 1);
    lsum1 += __shfl_xor_sync(0xffffffffu, lsum1, 2);
    float inv0 = 1.0f / lsum0, inv1 = 1.0f / lsum1;

    float* dst = g_attn + ((size_t)(b * Tq + q0)) * Dq + h * 64;
#pragma unroll
    for (int nt = 0; nt < 8; nt++) {
        *(float2*)(dst + nt * 8 + scp) = make_float2(acc[nt][0] * inv0, acc[nt][1] * inv0);
        *(float2*)(dst + 8 * Dq + nt * 8 + scp) = make_float2(acc[nt][2] * inv1, acc[nt][3] * inv1);
    }
}

// ---------------- launch ----------------
extern "C" void kernel_launch(void* const* d_in, const int* in_sizes, int n_in,
                              void* d_out, int out_size) {
    const float* x           = (const float*)d_in[0];
    const float* centers     = (const float*)d_in[1];
    const float* deltas      = (const float*)d_in[2];
    const float* log_scales  = (const float*)d_in[3];
    const float* log_amps    = (const float*)d_in[4];
    const float* movement    = (const float*)d_in[5];
    const float* temperature = (const float*)d_in[6];
    const float* qkv_w       = (const float*)d_in[7];
    const float* out_w       = (const float*)d_in[8];
    float* out = (float*)d_out;

    void *p_qkv = nullptr, *p_attn = nullptr;
    cudaGetSymbolAddress(&p_qkv, g_qkv);
    cudaGetSymbolAddress(&p_attn, g_attn);
    float* qkv_buf = (float*)p_qkv;
    float* attn_buf = (float*)p_attn;

    prep_kernel<<<64, 256>>>(centers, deltas, log_scales, log_amps, movement);

    // qkv = x @ qkv_w.T : N=4096, M=3072, K=1024
    mma_gemm_nt<<<dim3(3072 / 128, 4096 / 128), 256>>>(x, qkv_w, qkv_buf, Bq * Tq, 3 * Dq, Dq);

    splat_weights_kernel<<<dim3(Tq / 16, Hq, Bq * 2), 256>>>();

    flash_mma<<<dim3(Tq / 64, Hq, Bq), 128>>>(temperature);

    // out = attn @ out_w.T : N=4096, M=1024, K=1024
    mma_gemm_nt<<<dim3(1024 / 128, 4096 / 128), 256>>>(attn_buf, out_w, out, Bq * Tq, Dq, Dq);
}

// round 5
// speedup vs baseline: 2.8595x; 1.0955x over previous
#include <cuda_runtime.h>
#include <cuda_bf16.h>
#include <cstdint>

#define Bq 2
#define Tq 2048
#define Dq 1024
#define Hq 16
#define Sq 16
#define HDq 64

// ---------------- scratch (static device globals; no allocation) ----------------
__device__ __align__(128) float g_qkv[(size_t)Bq * Tq * 3 * Dq];   // (B*T, 3072)
__device__ __align__(128) float g_centers[Hq * Sq * HDq];
__device__ __align__(128) float g_invvar[Hq * Sq];
__device__ __align__(128) float g_amps[Hq * Sq];
__device__ __align__(128) float g_qw[(size_t)Bq * Hq * Tq * Sq];
__device__ __align__(128) float g_kw[(size_t)Bq * Hq * Tq * Sq];
__device__ __align__(128) float g_attn[(size_t)Bq * Tq * Dq];
// V fragments: [b][h][kt(32)][ks(4)][nt(8)][lane(32)] uint4{hi0,hi1,lo0,lo1}
__device__ __align__(128) uint4 g_vfrag[(size_t)Bq * Hq * 32 * 1024];
// KW fragments: [b][h][kt(32)][nt(8)][lane(32)] uint4{bh0,bh1,bl0,bl1}
__device__ __align__(128) uint4 g_kwfrag[(size_t)Bq * Hq * 32 * 256];

// ---------------- helpers ----------------
__device__ __forceinline__ void mma_bf16(float* c, const uint32_t* a, const uint32_t* b) {
    asm volatile(
        "mma.sync.aligned.m16n8k16.row.col.f32.bf16.bf16.f32 "
        "{%0,%1,%2,%3}, {%4,%5,%6,%7}, {%8,%9}, {%0,%1,%2,%3};"
        : "+f"(c[0]), "+f"(c[1]), "+f"(c[2]), "+f"(c[3])
        : "r"(a[0]), "r"(a[1]), "r"(a[2]), "r"(a[3]), "r"(b[0]), "r"(b[1]));
}

__device__ __forceinline__ uint32_t pack_bf16x2(float x, float y) {
    uint32_t r;
    asm("cvt.rn.bf16x2.f32 %0, %1, %2;" : "=r"(r) : "f"(y), "f"(x));
    return r;
}
__device__ __forceinline__ void split2(float x, float y, uint32_t& hi, uint32_t& lo) {
    hi = pack_bf16x2(x, y);
    float hx = __uint_as_float(hi << 16);
    float hy = __uint_as_float(hi & 0xffff0000u);
    lo = pack_bf16x2(x - hx, y - hy);
}

// ---------------- prep ----------------
__global__ void prep_kernel(const float* __restrict__ centers_in,
                            const float* __restrict__ deltas,
                            const float* __restrict__ log_scales,
                            const float* __restrict__ log_amps,
                            const float* __restrict__ movement_scale) {
    int tid = threadIdx.x;
    float ms = *movement_scale;
    float sig = 1.0f / (1.0f + expf(-ms));
    int i = blockIdx.x * 256 + tid;
    g_centers[i] = centers_in[i] + deltas[i] * sig * 0.2f;
    if (blockIdx.x == 0) {
        float sc = expf(log_scales[tid]);
        sc = fminf(fmaxf(sc, 0.01f), 2.0f);
        g_invvar[tid] = -0.5f / (sc * sc + 1e-8f);
        float am = expf(log_amps[tid]);
        g_amps[tid] = fminf(fmaxf(am, 1e-6f), 10.0f);
    }
}

// ---------------- bf16x3 tensor-core NT GEMM (unchanged) ----------------
__global__ __launch_bounds__(256) void mma_gemm_nt(const float* __restrict__ A,
                                                   const float* __restrict__ B,
                                                   float* __restrict__ C,
                                                   int N, int M, int K) {
    __shared__ uint32_t sA[4096];
    __shared__ uint32_t sB[4096];

    const int tid = threadIdx.x;
    const int warp = tid >> 5;
    const int lid = tid & 31;
    const int wm = warp >> 2;
    const int wn = warp & 3;
    const int bn = blockIdx.y * 128;
    const int bm = blockIdx.x * 128;

    const int lr = tid >> 3;
    const int kc4 = (tid & 7) << 2;

    float acc[4][4][4];
#pragma unroll
    for (int i = 0; i < 4; i++)
#pragma unroll
        for (int j = 0; j < 4; j++)
#pragma unroll
            for (int r = 0; r < 4; r++) acc[i][j][r] = 0.f;

    const int KCH = K >> 5;
    for (int kc = 0; kc < KCH; kc++) {
        __syncthreads();
#pragma unroll
        for (int i = 0; i < 4; i++) {
            int row = lr + 32 * i;
            float4 a = *(const float4*)(A + (size_t)(bn + row) * K + kc * 32 + kc4);
            int mt = row >> 4, rr = row & 15;
            {
                int kp = kc4, kk = kp & 15, ks = kp >> 4;
                int lane = ((rr & 7) << 2) | ((kk & 7) >> 1);
                int reg = (rr >> 3) + ((kk >> 3) << 1);
                int base = ((mt * 2 + ks) * 32 + lane) * 4 + reg;
                uint32_t hi, lo;
                split2(a.x, a.y, hi, lo);
                sA[base] = hi; sA[2048 + base] = lo;
            }
            {
                int kp = kc4 + 2, kk = kp & 15, ks = kp >> 4;
                int lane = ((rr & 7) << 2) | ((kk & 7) >> 1);
                int reg = (rr >> 3) + ((kk >> 3) << 1);
                int base = ((mt * 2 + ks) * 32 + lane) * 4 + reg;
                uint32_t hi, lo;
                split2(a.z, a.w, hi, lo);
                sA[base] = hi; sA[2048 + base] = lo;
            }
            float4 b = *(const float4*)(B + (size_t)(bm + row) * K + kc * 32 + kc4);
            int nt = row >> 3, nn = row & 7;
            {
                int kp = kc4, kk = kp & 15, ks = kp >> 4;
                int lane = (nn << 2) | ((kk & 7) >> 1);
                int reg = kk >> 3;
                int base = ((nt * 2 + ks) * 32 + lane) * 2 + reg;
                uint32_t hi, lo;
                split2(b.x, b.y, hi, lo);
                sB[base] = hi; sB[2048 + base] = lo;
            }
            {
                int kp = kc4 + 2, kk = kp & 15, ks = kp >> 4;
                int lane = (nn << 2) | ((kk & 7) >> 1);
                int reg = kk >> 3;
                int base = ((nt * 2 + ks) * 32 + lane) * 2 + reg;
                uint32_t hi, lo;
                split2(b.z, b.w, hi, lo);
                sB[base] = hi; sB[2048 + base] = lo;
            }
        }
        __syncthreads();

#pragma unroll
        for (int ks = 0; ks < 2; ks++) {
            uint32_t ahi[4][4], alo[4][4], bhi[4][2], blo[4][2];
#pragma unroll
            for (int i = 0; i < 4; i++) {
                int mt = wm * 4 + i;
                uint4 h = *(const uint4*)&sA[((mt * 2 + ks) * 32 + lid) * 4];
                ahi[i][0] = h.x; ahi[i][1] = h.y; ahi[i][2] = h.z; ahi[i][3] = h.w;
                uint4 l = *(const uint4*)&sA[2048 + ((mt * 2 + ks) * 32 + lid) * 4];
                alo[i][0] = l.x; alo[i][1] = l.y; alo[i][2] = l.z; alo[i][3] = l.w;
            }
#pragma unroll
            for (int j = 0; j < 4; j++) {
                int nt = wn * 4 + j;
                uint2 h = *(const uint2*)&sB[((nt * 2 + ks) * 32 + lid) * 2];
                bhi[j][0] = h.x; bhi[j][1] = h.y;
                uint2 l = *(const uint2*)&sB[2048 + ((nt * 2 + ks) * 32 + lid) * 2];
                blo[j][0] = l.x; blo[j][1] = l.y;
            }
#pragma unroll
            for (int i = 0; i < 4; i++)
#pragma unroll
                for (int j = 0; j < 4; j++) {
                    mma_bf16(acc[i][j], ahi[i], bhi[j]);
                    mma_bf16(acc[i][j], ahi[i], blo[j]);
                    mma_bf16(acc[i][j], alo[i], bhi[j]);
                }
        }
    }

#pragma unroll
    for (int i = 0; i < 4; i++) {
        int row0 = bn + wm * 64 + i * 16 + (lid >> 2);
#pragma unroll
        for (int j = 0; j < 4; j++) {
            int col = bm + wn * 32 + j * 8 + (lid & 3) * 2;
            *(float2*)(C + (size_t)row0 * M + col) = make_float2(acc[i][j][0], acc[i][j][1]);
            *(float2*)(C + (size_t)(row0 + 8) * M + col) = make_float2(acc[i][j][2], acc[i][j][3]);
        }
    }
}

// ---------------- splat gaussian weights ----------------
__global__ __launch_bounds__(256) void splat_weights_kernel() {
    __shared__ float sx[16][68];
    __shared__ float sc[16][68];
    const int tid = threadIdx.x;
    const int tb = blockIdx.x;
    const int h = blockIdx.y;
    const int b = blockIdx.z >> 1;
    const int which = blockIdx.z & 1;

    const int row = tid >> 4;
    const int d4 = (tid & 15) << 2;

    const int t = tb * 16 + row;
    float4 xv = *(const float4*)(g_qkv + ((size_t)(b * Tq + t) * 3 + which) * Dq + h * HDq + d4);
    *(float4*)&sx[row][d4] = xv;
    float4 cv = *(const float4*)(g_centers + (h * Sq + row) * HDq + d4);
    *(float4*)&sc[row][d4] = cv;
    __syncthreads();

    const int s = tid & 15;
    const int ti = tid >> 4;
    float acc = 0.f;
#pragma unroll
    for (int d = 0; d < 64; d++) {
        float diff = sx[ti][d] - sc[s][d];
        acc += diff * diff;
    }
    float w = __expf(acc * g_invvar[h * Sq + s]);
    if (which) w *= g_amps[h * Sq + s];
    float* dst = which ? g_kw : g_qw;
    dst[(((size_t)b * Hq + h) * Tq + (tb * 16 + ti)) * Sq + s] = w;
}

// ---------------- V fragment precompute ----------------
// grid (32, H, B), 256 threads. Writes bf16 hi/lo B-fragments for the AV mma.
__global__ __launch_bounds__(256) void v_frag_kernel() {
    __shared__ float sv[64][68];
    const int kt = blockIdx.x, h = blockIdx.y, b = blockIdx.z;
    const int tid = threadIdx.x;

#pragma unroll
    for (int i = 0; i < 4; i++) {
        int idx = i * 256 + tid;          // 1024 float4 loads (64 keys x 16 chunks)
        int row = idx >> 4;
        int c4 = (idx & 15) << 2;
        float4 v = *(const float4*)(g_qkv + ((size_t)(b * Tq + kt * 64 + row) * 3 + 2) * Dq +
                                    h * 64 + c4);
        *(float4*)&sv[row][c4] = v;
    }
    __syncthreads();

    uint4* dst = g_vfrag + (((size_t)(b * Hq + h) * 32 + kt) << 10);
#pragma unroll
    for (int i = 0; i < 4; i++) {
        int w = i * 256 + tid;
        int ks = w >> 8, rest = w & 255, nt = rest >> 5, lane = rest & 31;
        int d = nt * 8 + (lane >> 2);
        int k0 = ks * 16 + (lane & 3) * 2;
        uint32_t h0, l0, h1, l1;
        split2(sv[k0][d], sv[k0 + 1][d], h0, l0);
        split2(sv[k0 + 8][d], sv[k0 + 9][d], h1, l1);
        dst[w] = make_uint4(h0, h1, l0, l1);
    }
}

// ---------------- KW fragment precompute ----------------
// grid (32, H, B), 256 threads = exactly 8 nt x 32 lanes.
__global__ __launch_bounds__(256) void kw_frag_kernel() {
    const int kt = blockIdx.x, h = blockIdx.y, b = blockIdx.z;
    const int tid = threadIdx.x;
    const int nt = tid >> 5, lane = tid & 31;
    const float* kw = g_kw + (((size_t)b * Hq + h) * Tq + kt * 64 + nt * 8 + (lane >> 2)) * Sq;
    const int s0 = (lane & 3) * 2;
    uint32_t h0, l0, h1, l1;
    split2(__ldg(kw + s0), __ldg(kw + s0 + 1), h0, l0);
    split2(__ldg(kw + s0 + 8), __ldg(kw + s0 + 9), h1, l1);
    g_kwfrag[(((size_t)(b * Hq + h) * 32 + kt) << 8) + tid] = make_uint4(h0, h1, l0, l1);
}

// ---------------- flash attention: pure mma over precomputed fragments ----------------
// grid (T/64, H, B), 128 threads (4 warps), NO smem, NO syncthreads.
__global__ __launch_bounds__(128) void flash_mma(const float* __restrict__ temperature) {
    const int tid = threadIdx.x;
    const int warp = tid >> 5;
    const int lane = tid & 31;
    const int qt = blockIdx.x, h = blockIdx.y, b = blockIdx.z;

    const float temp = fminf(fmaxf(*temperature, 0.1f), 10.0f);
    const float invtemp = 1.0f / temp;
    float asum = 0.f;
#pragma unroll
    for (int s = 0; s < 16; s++) asum += g_amps[h * 16 + s];
    const float bound = asum * invtemp;

    const int r = lane >> 2;
    const int scp = (lane & 3) << 1;
    const int q0 = qt * 64 + warp * 16 + r;

    uint32_t qhi[4], qlo[4];
    {
        const float* qwp = g_qw + (((size_t)b * Hq + h) * Tq + q0) * Sq;
        float2 v;
        v = *(const float2*)(qwp + scp);
        split2(v.x * invtemp, v.y * invtemp, qhi[0], qlo[0]);
        v = *(const float2*)(qwp + 8 * Sq + scp);
        split2(v.x * invtemp, v.y * invtemp, qhi[1], qlo[1]);
        v = *(const float2*)(qwp + scp + 8);
        split2(v.x * invtemp, v.y * invtemp, qhi[2], qlo[2]);
        v = *(const float2*)(qwp + 8 * Sq + scp + 8);
        split2(v.x * invtemp, v.y * invtemp, qhi[3], qlo[3]);
    }

    float acc[8][4];
#pragma unroll
    for (int nt = 0; nt < 8; nt++)
#pragma unroll
        for (int i = 0; i < 4; i++) acc[nt][i] = 0.f;
    float lsum0 = 0.f, lsum1 = 0.f;

    const uint4* kwf = g_kwfrag + (((size_t)(b * Hq + h)) << 13) + lane;  // + kt*256 + nt*32
    const uint4* vfb = g_vfrag + (((size_t)(b * Hq + h)) << 15) + lane;   // + kt*1024 + (ks*8+nt)*32

    for (int kt = 0; kt < 32; kt++) {
        // QK logits + exp + pack P into A-fragments
        uint32_t ahi[4][4], alo[4][4];
        const uint4* kf = kwf + kt * 256;
#pragma unroll
        for (int nt = 0; nt < 8; nt++) {
            uint4 f = __ldg(kf + nt * 32);
            uint32_t bh[2] = {f.x, f.y};
            uint32_t bl[2] = {f.z, f.w};
            float c4[4] = {0.f, 0.f, 0.f, 0.f};
            mma_bf16(c4, qhi, bh);
            mma_bf16(c4, qhi, bl);
            mma_bf16(c4, qlo, bh);
            float p0 = __expf(c4[0] - bound);
            float p1 = __expf(c4[1] - bound);
            float p2 = __expf(c4[2] - bound);
            float p3 = __expf(c4[3] - bound);
            lsum0 += p0 + p1;
            lsum1 += p2 + p3;
            int ks = nt >> 1, ro = (nt & 1) * 2;
            split2(p0, p1, ahi[ks][ro], alo[ks][ro]);
            split2(p2, p3, ahi[ks][ro + 1], alo[ks][ro + 1]);
        }
        // AV
        const uint4* vf = vfb + kt * 1024;
#pragma unroll
        for (int ks = 0; ks < 4; ks++) {
#pragma unroll
            for (int nt = 0; nt < 8; nt++) {
                uint4 f = __ldg(vf + (ks * 8 + nt) * 32);
                uint32_t bh2[2] = {f.x, f.y};
                uint32_t bl2[2] = {f.z, f.w};
                mma_bf16(acc[nt], ahi[ks], bh2);
                mma_bf16(acc[nt], ahi[ks], bl2);
                mma_bf16(acc[nt], alo[ks], bh2);
            }
        }
    }

    lsum0 += __shfl_xor_sync(0xffffffffu, lsum0, 1);
    lsum0 += __shfl_xor_sync(0xffffffffu, lsum0, 2);
    lsum1 += __shfl_xor_sync(0xffffffffu, lsum1, 1);
    lsum1 += __shfl_xor_sync(0xffffffffu, lsum1, 2);
    float inv0 = 1.0f / lsum0, inv1 = 1.0f / lsum1;

    float* dst = g_attn + ((size_t)(b * Tq + q0)) * Dq + h * 64;
#pragma unroll
    for (int nt = 0; nt < 8; nt++) {
        *(float2*)(dst + nt * 8 + scp) = make_float2(acc[nt][0] * inv0, acc[nt][1] * inv0);
        *(float2*)(dst + 8 * Dq + nt * 8 + scp) = make_float2(acc[nt][2] * inv1, acc[nt][3] * inv1);
    }
}

// ---------------- launch ----------------
extern "C" void kernel_launch(void* const* d_in, const int* in_sizes, int n_in,
                              void* d_out, int out_size) {
    const float* x           = (const float*)d_in[0];
    const float* centers     = (const float*)d_in[1];
    const float* deltas      = (const float*)d_in[2];
    const float* log_scales  = (const float*)d_in[3];
    const float* log_amps    = (const float*)d_in[4];
    const float* movement    = (const float*)d_in[5];
    const float* temperature = (const float*)d_in[6];
    const float* qkv_w       = (const float*)d_in[7];
    const float* out_w       = (const float*)d_in[8];
    float* out = (float*)d_out;

    void *p_qkv = nullptr, *p_attn = nullptr;
    cudaGetSymbolAddress(&p_qkv, g_qkv);
    cudaGetSymbolAddress(&p_attn, g_attn);
    float* qkv_buf = (float*)p_qkv;
    float* attn_buf = (float*)p_attn;

    prep_kernel<<<64, 256>>>(centers, deltas, log_scales, log_amps, movement);

    // qkv = x @ qkv_w.T : N=4096, M=3072, K=1024
    mma_gemm_nt<<<dim3(3072 / 128, 4096 / 128), 256>>>(x, qkv_w, qkv_buf, Bq * Tq, 3 * Dq, Dq);

    v_frag_kernel<<<dim3(32, Hq, Bq), 256>>>();
    splat_weights_kernel<<<dim3(Tq / 16, Hq, Bq * 2), 256>>>();
    kw_frag_kernel<<<dim3(32, Hq, Bq), 256>>>();

    flash_mma<<<dim3(Tq / 64, Hq, Bq), 128>>>(temperature);

    // out = attn @ out_w.T : N=4096, M=1024, K=1024
    mma_gemm_nt<<<dim3(1024 / 128, 4096 / 128), 256>>>(attn_buf, out_w, out, Bq * Tq, Dq, Dq);
}

// round 6
// speedup vs baseline: 2.9758x; 1.0407x over previous
#include <cuda_runtime.h>
#include <cuda_bf16.h>
#include <cstdint>

#define Bq 2
#define Tq 2048
#define Dq 1024
#define Hq 16
#define Sq 16
#define HDq 64

// ---------------- scratch (static device globals; no allocation) ----------------
__device__ __align__(128) float g_qkv[(size_t)Bq * Tq * 3 * Dq];   // (B*T, 3072)
__device__ __align__(128) float g_centers[Hq * Sq * HDq];
__device__ __align__(128) float g_invvar[Hq * Sq];
__device__ __align__(128) float g_amps[Hq * Sq];
__device__ __align__(128) float g_qw[(size_t)Bq * Hq * Tq * Sq];
__device__ __align__(128) float g_kw[(size_t)Bq * Hq * Tq * Sq];
__device__ __align__(128) float g_attn[(size_t)Bq * Tq * Dq];
// V fragments: [b][h][kt(32)][ks(4)][nt(8)][lane(32)] uint4{hi0,hi1,lo0,lo1}
__device__ __align__(128) uint4 g_vfrag[(size_t)Bq * Hq * 32 * 1024];
// KW fragments: [b][h][kt(32)][nt(8)][lane(32)] uint4{bh0,bh1,bl0,bl1}
__device__ __align__(128) uint4 g_kwfrag[(size_t)Bq * Hq * 32 * 256];

// ---------------- helpers ----------------
__device__ __forceinline__ void mma_bf16(float* c, const uint32_t* a, const uint32_t* b) {
    asm volatile(
        "mma.sync.aligned.m16n8k16.row.col.f32.bf16.bf16.f32 "
        "{%0,%1,%2,%3}, {%4,%5,%6,%7}, {%8,%9}, {%0,%1,%2,%3};"
        : "+f"(c[0]), "+f"(c[1]), "+f"(c[2]), "+f"(c[3])
        : "r"(a[0]), "r"(a[1]), "r"(a[2]), "r"(a[3]), "r"(b[0]), "r"(b[1]));
}

__device__ __forceinline__ uint32_t pack_bf16x2(float x, float y) {
    uint32_t r;
    asm("cvt.rn.bf16x2.f32 %0, %1, %2;" : "=r"(r) : "f"(y), "f"(x));
    return r;
}
__device__ __forceinline__ void split2(float x, float y, uint32_t& hi, uint32_t& lo) {
    hi = pack_bf16x2(x, y);
    float hx = __uint_as_float(hi << 16);
    float hy = __uint_as_float(hi & 0xffff0000u);
    lo = pack_bf16x2(x - hx, y - hy);
}

// ---------------- prep ----------------
__global__ void prep_kernel(const float* __restrict__ centers_in,
                            const float* __restrict__ deltas,
                            const float* __restrict__ log_scales,
                            const float* __restrict__ log_amps,
                            const float* __restrict__ movement_scale) {
    int tid = threadIdx.x;
    float ms = *movement_scale;
    float sig = 1.0f / (1.0f + expf(-ms));
    int i = blockIdx.x * 256 + tid;
    g_centers[i] = centers_in[i] + deltas[i] * sig * 0.2f;
    if (blockIdx.x == 0) {
        float sc = expf(log_scales[tid]);
        sc = fminf(fmaxf(sc, 0.01f), 2.0f);
        g_invvar[tid] = -0.5f / (sc * sc + 1e-8f);
        float am = expf(log_amps[tid]);
        g_amps[tid] = fminf(fmaxf(am, 1e-6f), 10.0f);
    }
}

// ---------------- bf16x3 tensor-core NT GEMM, register double-buffered ----------------
__global__ __launch_bounds__(256) void mma_gemm_nt(const float* __restrict__ A,
                                                   const float* __restrict__ B,
                                                   float* __restrict__ C,
                                                   int N, int M, int K) {
    __shared__ uint32_t sA[4096];
    __shared__ uint32_t sB[4096];

    const int tid = threadIdx.x;
    const int warp = tid >> 5;
    const int lid = tid & 31;
    const int wm = warp >> 2;
    const int wn = warp & 3;
    const int bn = blockIdx.y * 128;
    const int bm = blockIdx.x * 128;

    const int lr = tid >> 3;
    const int kc4 = (tid & 7) << 2;

    float acc[4][4][4];
#pragma unroll
    for (int i = 0; i < 4; i++)
#pragma unroll
        for (int j = 0; j < 4; j++)
#pragma unroll
            for (int r = 0; r < 4; r++) acc[i][j][r] = 0.f;

    float4 ra[4], rb[4];
#pragma unroll
    for (int i = 0; i < 4; i++) {
        ra[i] = *(const float4*)(A + (size_t)(bn + lr + 32 * i) * K + kc4);
        rb[i] = *(const float4*)(B + (size_t)(bm + lr + 32 * i) * K + kc4);
    }

    const int KCH = K >> 5;
    for (int kc = 0; kc < KCH; kc++) {
        __syncthreads();
        // ---- split + fragment-order store from registers ----
#pragma unroll
        for (int i = 0; i < 4; i++) {
            int row = lr + 32 * i;
            int mt = row >> 4, rr = row & 15;
            {
                int kp = kc4, kk = kp & 15, ks = kp >> 4;
                int lane = ((rr & 7) << 2) | ((kk & 7) >> 1);
                int reg = (rr >> 3) + ((kk >> 3) << 1);
                int base = ((mt * 2 + ks) * 32 + lane) * 4 + reg;
                uint32_t hi, lo;
                split2(ra[i].x, ra[i].y, hi, lo);
                sA[base] = hi; sA[2048 + base] = lo;
            }
            {
                int kp = kc4 + 2, kk = kp & 15, ks = kp >> 4;
                int lane = ((rr & 7) << 2) | ((kk & 7) >> 1);
                int reg = (rr >> 3) + ((kk >> 3) << 1);
                int base = ((mt * 2 + ks) * 32 + lane) * 4 + reg;
                uint32_t hi, lo;
                split2(ra[i].z, ra[i].w, hi, lo);
                sA[base] = hi; sA[2048 + base] = lo;
            }
            int nt = row >> 3, nn = row & 7;
            {
                int kp = kc4, kk = kp & 15, ks = kp >> 4;
                int lane = (nn << 2) | ((kk & 7) >> 1);
                int reg = kk >> 3;
                int base = ((nt * 2 + ks) * 32 + lane) * 2 + reg;
                uint32_t hi, lo;
                split2(rb[i].x, rb[i].y, hi, lo);
                sB[base] = hi; sB[2048 + base] = lo;
            }
            {
                int kp = kc4 + 2, kk = kp & 15, ks = kp >> 4;
                int lane = (nn << 2) | ((kk & 7) >> 1);
                int reg = kk >> 3;
                int base = ((nt * 2 + ks) * 32 + lane) * 2 + reg;
                uint32_t hi, lo;
                split2(rb[i].z, rb[i].w, hi, lo);
                sB[base] = hi; sB[2048 + base] = lo;
            }
        }
        __syncthreads();

        // ---- prefetch next K-chunk (overlaps with mma below) ----
        if (kc + 1 < KCH) {
#pragma unroll
            for (int i = 0; i < 4; i++) {
                ra[i] = *(const float4*)(A + (size_t)(bn + lr + 32 * i) * K + (kc + 1) * 32 + kc4);
                rb[i] = *(const float4*)(B + (size_t)(bm + lr + 32 * i) * K + (kc + 1) * 32 + kc4);
            }
        }

        // ---- consume ----
#pragma unroll
        for (int ks = 0; ks < 2; ks++) {
            uint32_t ahi[4][4], alo[4][4], bhi[4][2], blo[4][2];
#pragma unroll
            for (int i = 0; i < 4; i++) {
                int mt = wm * 4 + i;
                uint4 h = *(const uint4*)&sA[((mt * 2 + ks) * 32 + lid) * 4];
                ahi[i][0] = h.x; ahi[i][1] = h.y; ahi[i][2] = h.z; ahi[i][3] = h.w;
                uint4 l = *(const uint4*)&sA[2048 + ((mt * 2 + ks) * 32 + lid) * 4];
                alo[i][0] = l.x; alo[i][1] = l.y; alo[i][2] = l.z; alo[i][3] = l.w;
            }
#pragma unroll
            for (int j = 0; j < 4; j++) {
                int nt = wn * 4 + j;
                uint2 h = *(const uint2*)&sB[((nt * 2 + ks) * 32 + lid) * 2];
                bhi[j][0] = h.x; bhi[j][1] = h.y;
                uint2 l = *(const uint2*)&sB[2048 + ((nt * 2 + ks) * 32 + lid) * 2];
                blo[j][0] = l.x; blo[j][1] = l.y;
            }
#pragma unroll
            for (int i = 0; i < 4; i++)
#pragma unroll
                for (int j = 0; j < 4; j++) {
                    mma_bf16(acc[i][j], ahi[i], bhi[j]);
                    mma_bf16(acc[i][j], ahi[i], blo[j]);
                    mma_bf16(acc[i][j], alo[i], bhi[j]);
                }
        }
    }

#pragma unroll
    for (int i = 0; i < 4; i++) {
        int row0 = bn + wm * 64 + i * 16 + (lid >> 2);
#pragma unroll
        for (int j = 0; j < 4; j++) {
            int col = bm + wn * 32 + j * 8 + (lid & 3) * 2;
            *(float2*)(C + (size_t)row0 * M + col) = make_float2(acc[i][j][0], acc[i][j][1]);
            *(float2*)(C + (size_t)(row0 + 8) * M + col) = make_float2(acc[i][j][2], acc[i][j][3]);
        }
    }
}

// ---------------- splat gaussian weights ----------------
__global__ __launch_bounds__(256) void splat_weights_kernel() {
    __shared__ float sx[16][68];
    __shared__ float sc[16][68];
    const int tid = threadIdx.x;
    const int tb = blockIdx.x;
    const int h = blockIdx.y;
    const int b = blockIdx.z >> 1;
    const int which = blockIdx.z & 1;

    const int row = tid >> 4;
    const int d4 = (tid & 15) << 2;

    const int t = tb * 16 + row;
    float4 xv = *(const float4*)(g_qkv + ((size_t)(b * Tq + t) * 3 + which) * Dq + h * HDq + d4);
    *(float4*)&sx[row][d4] = xv;
    float4 cv = *(const float4*)(g_centers + (h * Sq + row) * HDq + d4);
    *(float4*)&sc[row][d4] = cv;
    __syncthreads();

    const int s = tid & 15;
    const int ti = tid >> 4;
    float acc = 0.f;
#pragma unroll
    for (int d = 0; d < 64; d++) {
        float diff = sx[ti][d] - sc[s][d];
        acc += diff * diff;
    }
    float w = __expf(acc * g_invvar[h * Sq + s]);
    if (which) w *= g_amps[h * Sq + s];
    float* dst = which ? g_kw : g_qw;
    dst[(((size_t)b * Hq + h) * Tq + (tb * 16 + ti)) * Sq + s] = w;
}

// ---------------- V fragment precompute ----------------
__global__ __launch_bounds__(256) void v_frag_kernel() {
    __shared__ float sv[64][68];
    const int kt = blockIdx.x, h = blockIdx.y, b = blockIdx.z;
    const int tid = threadIdx.x;

#pragma unroll
    for (int i = 0; i < 4; i++) {
        int idx = i * 256 + tid;
        int row = idx >> 4;
        int c4 = (idx & 15) << 2;
        float4 v = *(const float4*)(g_qkv + ((size_t)(b * Tq + kt * 64 + row) * 3 + 2) * Dq +
                                    h * 64 + c4);
        *(float4*)&sv[row][c4] = v;
    }
    __syncthreads();

    uint4* dst = g_vfrag + (((size_t)(b * Hq + h) * 32 + kt) << 10);
#pragma unroll
    for (int i = 0; i < 4; i++) {
        int w = i * 256 + tid;
        int ks = w >> 8, rest = w & 255, nt = rest >> 5, lane = rest & 31;
        int d = nt * 8 + (lane >> 2);
        int k0 = ks * 16 + (lane & 3) * 2;
        uint32_t h0, l0, h1, l1;
        split2(sv[k0][d], sv[k0 + 1][d], h0, l0);
        split2(sv[k0 + 8][d], sv[k0 + 9][d], h1, l1);
        dst[w] = make_uint4(h0, h1, l0, l1);
    }
}

// ---------------- KW fragment precompute ----------------
__global__ __launch_bounds__(256) void kw_frag_kernel() {
    const int kt = blockIdx.x, h = blockIdx.y, b = blockIdx.z;
    const int tid = threadIdx.x;
    const int nt = tid >> 5, lane = tid & 31;
    const float* kw = g_kw + (((size_t)b * Hq + h) * Tq + kt * 64 + nt * 8 + (lane >> 2)) * Sq;
    const int s0 = (lane & 3) * 2;
    uint32_t h0, l0, h1, l1;
    split2(__ldg(kw + s0), __ldg(kw + s0 + 1), h0, l0);
    split2(__ldg(kw + s0 + 8), __ldg(kw + s0 + 9), h1, l1);
    g_kwfrag[(((size_t)(b * Hq + h) * 32 + kt) << 8) + tid] = make_uint4(h0, h1, l0, l1);
}

// ---------------- flash attention: pure mma over precomputed fragments ----------------
// QK = bf16x3 (accuracy-critical for exp); P = single bf16 (self-consistent l);
// V = bf16 hi+lo. 88 HMMA/warp/tile instead of 120.
__global__ __launch_bounds__(128) void flash_mma(const float* __restrict__ temperature) {
    const int tid = threadIdx.x;
    const int warp = tid >> 5;
    const int lane = tid & 31;
    const int qt = blockIdx.x, h = blockIdx.y, b = blockIdx.z;

    const float temp = fminf(fmaxf(*temperature, 0.1f), 10.0f);
    const float invtemp = 1.0f / temp;
    float asum = 0.f;
#pragma unroll
    for (int s = 0; s < 16; s++) asum += g_amps[h * 16 + s];
    const float bound = asum * invtemp;

    const int r = lane >> 2;
    const int scp = (lane & 3) << 1;
    const int q0 = qt * 64 + warp * 16 + r;

    uint32_t qhi[4], qlo[4];
    {
        const float* qwp = g_qw + (((size_t)b * Hq + h) * Tq + q0) * Sq;
        float2 v;
        v = *(const float2*)(qwp + scp);
        split2(v.x * invtemp, v.y * invtemp, qhi[0], qlo[0]);
        v = *(const float2*)(qwp + 8 * Sq + scp);
        split2(v.x * invtemp, v.y * invtemp, qhi[1], qlo[1]);
        v = *(const float2*)(qwp + scp + 8);
        split2(v.x * invtemp, v.y * invtemp, qhi[2], qlo[2]);
        v = *(const float2*)(qwp + 8 * Sq + scp + 8);
        split2(v.x * invtemp, v.y * invtemp, qhi[3], qlo[3]);
    }

    float acc[8][4];
#pragma unroll
    for (int nt = 0; nt < 8; nt++)
#pragma unroll
        for (int i = 0; i < 4; i++) acc[nt][i] = 0.f;
    float lsum0 = 0.f, lsum1 = 0.f;

    const uint4* kwf = g_kwfrag + (((size_t)(b * Hq + h)) << 13) + lane;
    const uint4* vfb = g_vfrag + (((size_t)(b * Hq + h)) << 15) + lane;

    for (int kt = 0; kt < 32; kt++) {
        // QK logits + exp + pack P (bf16, self-consistent l) into A-fragments
        uint32_t ap[4][4];
        const uint4* kf = kwf + kt * 256;
#pragma unroll
        for (int nt = 0; nt < 8; nt++) {
            uint4 f = __ldg(kf + nt * 32);
            uint32_t bh[2] = {f.x, f.y};
            uint32_t bl[2] = {f.z, f.w};
            float c4[4] = {0.f, 0.f, 0.f, 0.f};
            mma_bf16(c4, qhi, bh);
            mma_bf16(c4, qhi, bl);
            mma_bf16(c4, qlo, bh);
            float p0 = __expf(c4[0] - bound);
            float p1 = __expf(c4[1] - bound);
            float p2 = __expf(c4[2] - bound);
            float p3 = __expf(c4[3] - bound);
            uint32_t P01 = pack_bf16x2(p0, p1);
            uint32_t P23 = pack_bf16x2(p2, p3);
            // accumulate l from the SAME rounded values used in AV
            lsum0 += __uint_as_float(P01 << 16) + __uint_as_float(P01 & 0xffff0000u);
            lsum1 += __uint_as_float(P23 << 16) + __uint_as_float(P23 & 0xffff0000u);
            int ks = nt >> 1, ro = (nt & 1) * 2;
            ap[ks][ro] = P01;
            ap[ks][ro + 1] = P23;
        }
        // AV: 2 mma per tile (V hi + V lo), P unsplit
        const uint4* vf = vfb + kt * 1024;
#pragma unroll
        for (int ks = 0; ks < 4; ks++) {
#pragma unroll
            for (int nt = 0; nt < 8; nt++) {
                uint4 f = __ldg(vf + (ks * 8 + nt) * 32);
                uint32_t bh2[2] = {f.x, f.y};
                uint32_t bl2[2] = {f.z, f.w};
                mma_bf16(acc[nt], ap[ks], bh2);
                mma_bf16(acc[nt], ap[ks], bl2);
            }
        }
    }

    lsum0 += __shfl_xor_sync(0xffffffffu, lsum0, 1);
    lsum0 += __shfl_xor_sync(0xffffffffu, lsum0, 2);
    lsum1 += __shfl_xor_sync(0xffffffffu, lsum1, 1);
    lsum1 += __shfl_xor_sync(0xffffffffu, lsum1, 2);
    float inv0 = 1.0f / lsum0, inv1 = 1.0f / lsum1;

    float* dst = g_attn + ((size_t)(b * Tq + q0)) * Dq + h * 64;
#pragma unroll
    for (int nt = 0; nt < 8; nt++) {
        *(float2*)(dst + nt * 8 + scp) = make_float2(acc[nt][0] * inv0, acc[nt][1] * inv0);
        *(float2*)(dst + 8 * Dq + nt * 8 + scp) = make_float2(acc[nt][2] * inv1, acc[nt][3] * inv1);
    }
}

// ---------------- launch ----------------
extern "C" void kernel_launch(void* const* d_in, const int* in_sizes, int n_in,
                              void* d_out, int out_size) {
    const float* x           = (const float*)d_in[0];
    const float* centers     = (const float*)d_in[1];
    const float* deltas      = (const float*)d_in[2];
    const float* log_scales  = (const float*)d_in[3];
    const float* log_amps    = (const float*)d_in[4];
    const float* movement    = (const float*)d_in[5];
    const float* temperature = (const float*)d_in[6];
    const float* qkv_w       = (const float*)d_in[7];
    const float* out_w       = (const float*)d_in[8];
    float* out = (float*)d_out;

    void *p_qkv = nullptr, *p_attn = nullptr;
    cudaGetSymbolAddress(&p_qkv, g_qkv);
    cudaGetSymbolAddress(&p_attn, g_attn);
    float* qkv_buf = (float*)p_qkv;
    float* attn_buf = (float*)p_attn;

    prep_kernel<<<64, 256>>>(centers, deltas, log_scales, log_amps, movement);

    // qkv = x @ qkv_w.T : N=4096, M=3072, K=1024
    mma_gemm_nt<<<dim3(3072 / 128, 4096 / 128), 256>>>(x, qkv_w, qkv_buf, Bq * Tq, 3 * Dq, Dq);

    v_frag_kernel<<<dim3(32, Hq, Bq), 256>>>();
    splat_weights_kernel<<<dim3(Tq / 16, Hq, Bq * 2), 256>>>();
    kw_frag_kernel<<<dim3(32, Hq, Bq), 256>>>();

    flash_mma<<<dim3(Tq / 64, Hq, Bq), 128>>>(temperature);

    // out = attn @ out_w.T : N=4096, M=1024, K=1024
    mma_gemm_nt<<<dim3(1024 / 128, 4096 / 128), 256>>>(attn_buf, out_w, out, Bq * Tq, Dq, Dq);
}